// round 7
// baseline (speedup 1.0000x reference)
#include <cuda_runtime.h>
#include <math.h>

#define B 16
#define N 32
#define C 512
#define FEAT 224

#define HW0 784
#define HW1 196
#define HW2 49
#define OUT_ROW (C*(HW0+HW1+HW2))
#define OUT_OFF1 (C*HW0)         // 401408
#define OUT_OFF2 (C*(HW0+HW1))   // 501760
#define MAXSEG 96

// ---------------- scratch (no allocations allowed) ----------------
__device__ float    g_wx[B][MAXSEG];
__device__ unsigned g_colm[B][MAXSEG];
__device__ int      g_cellx[B][MAXSEG];
__device__ int      g_nsegx[B];
__device__ float    g_wy[B][MAXSEG];
__device__ unsigned g_rowm[B][MAXSEG];
__device__ int      g_bandidx[B][29];
__device__ float    g_sum28[B][HW0];     // per-8x8-tile sum of sigmoid
__device__ float    g_logits[3 * B * C];
__device__ float    g_red[2 * 3 * B];    // {smax, ssum} per group
__device__ unsigned g_cnt[3 * B];        // monotonic ticket (never reset)
__device__ unsigned g_flag[3 * B];       // monotonic done flag (never reset)

// ---------------- K0: per-batch segment tables --------------------------
// Breakpoints = box edges U multiples of 8, so segments never straddle
// 8-wide pool cells / 8-tall pool bands.
__global__ void seg_kernel(const float* __restrict__ boxes) {
    int b = blockIdx.x;
    int t = threadIdx.x;
    __shared__ int sbx[N * 4];
    __shared__ unsigned char flag[FEAT];
    __shared__ int segstart[MAXSEG];
    __shared__ int woff[8];
    __shared__ int snseg;

    if (t < N * 4) sbx[t] = (int)floorf(boxes[b * N * 4 + t] * (float)FEAT);
    __syncthreads();

    for (int axis = 0; axis < 2; axis++) {
        if (t < FEAT) flag[t] = ((t & 7) == 0);
        __syncthreads();
        if (t < N) {
            int e1 = sbx[4 * t + axis];
            int e2 = sbx[4 * t + 2 + axis];
            if (e1 >= 0 && e1 < FEAT) flag[e1] = 1;
            if (e2 >= 0 && e2 < FEAT) flag[e2] = 1;
        }
        __syncthreads();

        unsigned bal = 0;
        int lane = t & 31, w = t >> 5;
        if (t < FEAT) {
            bal = __ballot_sync(0xffffffffu, flag[t] != 0);
            if (lane == 0) woff[w] = __popc(bal);
        }
        __syncthreads();
        if (t == 0) {
            int run = 0;
            for (int i = 0; i < 7; i++) { int c = woff[i]; woff[i] = run; run += c; }
            snseg = run;
        }
        __syncthreads();
        if (t < FEAT && flag[t]) {
            int idx = woff[w] + __popc(bal & ((1u << lane) - 1u));
            segstart[idx] = t;
        }
        __syncthreads();

        int nseg = snseg;
        if (t < nseg) {
            int s = segstart[t];
            int wd = ((t + 1 < nseg) ? segstart[t + 1] : FEAT) - s;
            unsigned m = 0;
#pragma unroll
            for (int n = 0; n < N; n++)
                m |= (unsigned)(s >= sbx[4 * n + axis] && s < sbx[4 * n + 2 + axis]) << n;
            if (axis == 0) {
                g_wx[b][t] = (float)wd;
                g_colm[b][t] = m;
                g_cellx[b][t] = s >> 3;
            } else {
                g_wy[b][t] = (float)wd;
                g_rowm[b][t] = m;
                if ((s & 7) == 0) g_bandidx[b][s >> 3] = t;
            }
        }
        if (t == 0) {
            if (axis == 0) g_nsegx[b] = nseg;
            else g_bandidx[b][28] = nseg;
        }
        __syncthreads();
    }
}

// ---------------- K1: rectangle eval -> 8x8 tile sums ------------------
__global__ void tile_kernel(const float* __restrict__ confs) {
    int band = blockIdx.x, b = blockIdx.y;
    int t = threadIdx.x;
    __shared__ float swx[MAXSEG];
    __shared__ unsigned scolm[MAXSEG];
    __shared__ int scell[MAXSEG];
    __shared__ float swy[72];
    __shared__ unsigned srowm[72];
    __shared__ float sconf[N];
    __shared__ float stile[28];
    __shared__ int snx, sny, si0;

    if (t < N) sconf[t] = confs[b * N + t];
    if (t == 0) {
        snx = g_nsegx[b];
        int i0 = g_bandidx[b][band];
        si0 = i0;
        sny = g_bandidx[b][band + 1] - i0;
    }
    if (t < 28) stile[t] = 0.f;
    __syncthreads();

    int nx = snx, ny = sny, i0 = si0;
    for (int i = t; i < nx; i += 256) {
        swx[i] = g_wx[b][i];
        scolm[i] = g_colm[b][i];
        scell[i] = g_cellx[b][i];
    }
    for (int i = t; i < ny; i += 256) {
        swy[i] = g_wy[b][i0 + i];
        srowm[i] = g_rowm[b][i0 + i];
    }
    __syncthreads();

    int pairs = nx * ny;
    for (int p = t; p < pairs; p += 256) {
        int ys = p / nx, xs = p - ys * nx;
        unsigned m = srowm[ys] & scolm[xs];
        float v = 0.f;
        while (m) {
            int i = __ffs(m) - 1;
            v += sconf[i];
            m &= m - 1;
        }
        float sg = __fdividef(1.f, 1.f + __expf(-v));
        atomicAdd(&stile[scell[xs]], swy[ys] * swx[xs] * sg);
    }
    __syncthreads();
    if (t < 28) g_sum28[b][band * 28 + t] = stile[t];
}

// -------- K2: fused logits + group softmax + scale ------------------------
// grid = (C/8, B, 3), 256 threads = 8 warps; each warp owns one channel.
// Group (l,b) = 64 blocks. Device-side group barrier via monotonic counters.
__global__ void fused_kernel(const float* __restrict__ f0,
                             const float* __restrict__ f1,
                             const float* __restrict__ f2,
                             float* __restrict__ out) {
    int l = blockIdx.z, b = blockIdx.y;
    int g = l * B + b;
    __shared__ __align__(16) float satt[HW0];

    int warp = threadIdx.x >> 5, lane = threadIdx.x & 31;
    int c = blockIdx.x * 8 + warp;
    int t = threadIdx.x;
    float acc = 0.f;
    const float* gs = g_sum28[b];

    if (l == 0) {
        for (int i = t; i < HW0; i += 256) satt[i] = gs[i] * (1.f / 64.f);
        __syncthreads();
        const float4* fp = (const float4*)(f0 + ((size_t)(b * C + c)) * HW0);
        const float4* ap = (const float4*)satt;
#pragma unroll
        for (int k = 0; k < 7; k++) {
            int i = lane + 32 * k;
            if (i < HW0 / 4) {
                float4 v = fp[i], a = ap[i];
                acc = fmaf(v.x, a.x, acc);
                acc = fmaf(v.y, a.y, acc);
                acc = fmaf(v.z, a.z, acc);
                acc = fmaf(v.w, a.w, acc);
            }
        }
    } else if (l == 1) {
        if (t < HW1) {
            int ay = t / 14, ax = t % 14;
            int base = (2 * ay) * 28 + 2 * ax;
            float s = gs[base] + gs[base + 1] + gs[base + 28] + gs[base + 29];
            satt[t] = s * (1.f / 256.f);
        }
        __syncthreads();
        const float4* fp = (const float4*)(f1 + ((size_t)(b * C + c)) * HW1);
        const float4* ap = (const float4*)satt;
#pragma unroll
        for (int k = 0; k < 2; k++) {
            int i = lane + 32 * k;
            if (i < HW1 / 4) {
                float4 v = fp[i], a = ap[i];
                acc = fmaf(v.x, a.x, acc);
                acc = fmaf(v.y, a.y, acc);
                acc = fmaf(v.z, a.z, acc);
                acc = fmaf(v.w, a.w, acc);
            }
        }
    } else {
        if (t < HW2) {
            int ay = t / 7, ax = t % 7;
            float s = 0.f;
#pragma unroll
            for (int iy = 0; iy < 4; iy++)
#pragma unroll
                for (int ix = 0; ix < 4; ix++)
                    s += gs[(4 * ay + iy) * 28 + 4 * ax + ix];
            satt[t] = s * (1.f / 1024.f);
        }
        __syncthreads();
        const float* fp = f2 + ((size_t)(b * C + c)) * HW2;
#pragma unroll
        for (int k = 0; k < 2; k++) {
            int i = lane + 32 * k;
            if (i < HW2) acc = fmaf(fp[i], satt[i], acc);
        }
    }

    // butterfly: every lane ends with the full dot product
#pragma unroll
    for (int o = 16; o > 0; o >>= 1) acc += __shfl_xor_sync(0xffffffffu, acc, o);
    int base = g * C;
    if (lane == 0) g_logits[base + c] = acc;

    // ---- arrive on group ticket (monotonic; replay index R = old>>6) ----
    __shared__ unsigned s_replay;
    __shared__ int s_last;
    __syncthreads();
    if (t == 0) {
        __threadfence();
        unsigned old = atomicAdd(&g_cnt[g], 1u);
        s_replay = old >> 6;
        s_last = ((old & 63u) == 63u);
    }
    __syncthreads();

    // ---- last block of group: softmax reduction, publish {smax, ssum} ----
    if (s_last) {
        __shared__ float red[8];
        __shared__ float smaxs;
        float x0 = g_logits[base + t];
        float x1 = g_logits[base + t + 256];
        float m = fmaxf(x0, x1);
#pragma unroll
        for (int o = 16; o > 0; o >>= 1) m = fmaxf(m, __shfl_xor_sync(0xffffffffu, m, o));
        if (lane == 0) red[warp] = m;
        __syncthreads();
        if (t == 0) {
            float mm = red[0];
#pragma unroll
            for (int i = 1; i < 8; i++) mm = fmaxf(mm, red[i]);
            smaxs = mm;
        }
        __syncthreads();
        float mm = smaxs;
        float s = __expf(x0 - mm) + __expf(x1 - mm);
#pragma unroll
        for (int o = 16; o > 0; o >>= 1) s += __shfl_xor_sync(0xffffffffu, s, o);
        if (lane == 0) red[warp] = s;
        __syncthreads();
        if (t == 0) {
            float ss = 0.f;
#pragma unroll
            for (int i = 0; i < 8; i++) ss += red[i];
            g_red[2 * g] = mm;
            g_red[2 * g + 1] = ss;
            __threadfence();
            atomicAdd(&g_flag[g], 1u);
        }
    }

    // ---- wait for group result ----
    if (t == 0) {
        unsigned target = s_replay + 1u;
        while (*((volatile unsigned*)&g_flag[g]) < target) __nanosleep(64);
    }
    __syncthreads();
    __threadfence();

    float smax = *((volatile float*)&g_red[2 * g]);
    float ssum = *((volatile float*)&g_red[2 * g + 1]);
    float w = __expf(acc - smax) * __fdividef(1.f, ssum);

    // ---- scale this warp's channel row (re-read hits L1/L2) ----
    int row = b * C + c;
    if (l == 0) {
        const float4* src = (const float4*)(f0 + (size_t)row * HW0);
        float4* dst = (float4*)(out + (size_t)b * OUT_ROW + (size_t)c * HW0);
#pragma unroll
        for (int k = 0; k < 7; k++) {
            int i = lane + 32 * k;
            if (i < HW0 / 4) {
                float4 v = src[i];
                v.x *= w; v.y *= w; v.z *= w; v.w *= w;
                dst[i] = v;
            }
        }
    } else if (l == 1) {
        const float4* src = (const float4*)(f1 + (size_t)row * HW1);
        float4* dst = (float4*)(out + (size_t)b * OUT_ROW + OUT_OFF1 + (size_t)c * HW1);
#pragma unroll
        for (int k = 0; k < 2; k++) {
            int i = lane + 32 * k;
            if (i < HW1 / 4) {
                float4 v = src[i];
                v.x *= w; v.y *= w; v.z *= w; v.w *= w;
                dst[i] = v;
            }
        }
    } else {
        const float* src = f2 + (size_t)row * HW2;
        float* dst = out + (size_t)b * OUT_ROW + OUT_OFF2 + (size_t)c * HW2;
#pragma unroll
        for (int k = 0; k < 2; k++) {
            int i = lane + 32 * k;
            if (i < HW2) dst[i] = src[i] * w;
        }
    }
}

extern "C" void kernel_launch(void* const* d_in, const int* in_sizes, int n_in,
                              void* d_out, int out_size) {
    const float* confs = (const float*)d_in[0];
    const float* boxes = (const float*)d_in[1];
    const float* f0 = (const float*)d_in[2];
    const float* f1 = (const float*)d_in[3];
    const float* f2 = (const float*)d_in[4];
    float* out = (float*)d_out;

    seg_kernel<<<B, 256>>>(boxes);
    tile_kernel<<<dim3(28, B), 256>>>(confs);
    fused_kernel<<<dim3(C / 8, B, 3), 256>>>(f0, f1, f2, out);
}

// round 8
// speedup vs baseline: 1.6749x; 1.6749x over previous
#include <cuda_runtime.h>
#include <math.h>

#define B 16
#define N 32
#define C 512
#define FEAT 224

#define HW0 784
#define HW1 196
#define HW2 49
#define OUT_ROW (C*(HW0+HW1+HW2))
#define OUT_OFF1 (C*HW0)         // 401408
#define OUT_OFF2 (C*(HW0+HW1))   // 501760
#define MAXSEG 96

// ---------------- scratch (no allocations allowed) ----------------
__device__ float    g_wx[B][MAXSEG];
__device__ unsigned g_colm[B][MAXSEG];
__device__ int      g_cellx[B][MAXSEG];
__device__ int      g_nsegx[B];
__device__ float    g_wy[B][MAXSEG];
__device__ unsigned g_rowm[B][MAXSEG];
__device__ int      g_bandidx[B][29];
__device__ float    g_sum28[B][HW0];   // per-8x8-tile sum of sigmoid
__device__ float    g_logits[3 * B * C];
__device__ float    g_weights[3 * B * C];
__device__ int      g_cnt[3 * B];      // zero-init; reset by last block each run

// ---------------- K0: per-batch segment tables, both axes in parallel ----
// grid = B, 448 threads: threads [0,224) handle x-axis, [224,448) y-axis.
__global__ void seg_kernel(const float* __restrict__ boxes) {
    int b = blockIdx.x;
    int t = threadIdx.x;
    int axis = (t >= 224);
    int u = t - axis * 224;               // position 0..223 within axis
    int lane = t & 31;
    int wl = (t >> 5) - axis * 7;         // warp index within axis (0..6)

    __shared__ int sbx[N * 4];
    __shared__ unsigned char flag[2][FEAT];
    __shared__ int segstart[2][MAXSEG];
    __shared__ int woff[2][8];
    __shared__ int snseg[2];

    if (t < N * 4) sbx[t] = (int)floorf(boxes[b * N * 4 + t] * (float)FEAT);
    flag[axis][u] = ((u & 7) == 0);
    __syncthreads();

    if (u < N) {
        int e1 = sbx[4 * u + axis];
        int e2 = sbx[4 * u + 2 + axis];
        if (e1 >= 0 && e1 < FEAT) flag[axis][e1] = 1;
        if (e2 >= 0 && e2 < FEAT) flag[axis][e2] = 1;
    }
    __syncthreads();

    unsigned bal = __ballot_sync(0xffffffffu, flag[axis][u] != 0);
    if (lane == 0) woff[axis][wl] = __popc(bal);
    __syncthreads();
    if (u == 0) {
        int run = 0;
        for (int i = 0; i < 7; i++) { int c = woff[axis][i]; woff[axis][i] = run; run += c; }
        snseg[axis] = run;
    }
    __syncthreads();
    if (flag[axis][u])
        segstart[axis][woff[axis][wl] + __popc(bal & ((1u << lane) - 1u))] = u;
    __syncthreads();

    int nseg = snseg[axis];
    if (u < nseg) {
        int s = segstart[axis][u];
        int wd = ((u + 1 < nseg) ? segstart[axis][u + 1] : FEAT) - s;
        unsigned m = 0;
#pragma unroll
        for (int n = 0; n < N; n++)
            m |= (unsigned)(s >= sbx[4 * n + axis] && s < sbx[4 * n + 2 + axis]) << n;
        if (axis == 0) {
            g_wx[b][u] = (float)wd;
            g_colm[b][u] = m;
            g_cellx[b][u] = s >> 3;
        } else {
            g_wy[b][u] = (float)wd;
            g_rowm[b][u] = m;
            if ((s & 7) == 0) g_bandidx[b][s >> 3] = u;
        }
    }
    if (u == 0) {
        if (axis == 0) g_nsegx[b] = nseg;
        else g_bandidx[b][28] = nseg;
    }
}

// ---------------- K1: rectangle eval -> 8x8 tile sums ------------------
__global__ void tile_kernel(const float* __restrict__ confs) {
    int band = blockIdx.x, b = blockIdx.y;
    int t = threadIdx.x;
    __shared__ float swx[MAXSEG];
    __shared__ unsigned scolm[MAXSEG];
    __shared__ int scell[MAXSEG];
    __shared__ float swy[72];
    __shared__ unsigned srowm[72];
    __shared__ float sconf[N];
    __shared__ float stile[28];
    __shared__ int snx, sny, si0;

    if (t < N) sconf[t] = confs[b * N + t];
    if (t == 0) {
        snx = g_nsegx[b];
        int i0 = g_bandidx[b][band];
        si0 = i0;
        sny = g_bandidx[b][band + 1] - i0;
    }
    if (t < 28) stile[t] = 0.f;
    __syncthreads();

    int nx = snx, ny = sny, i0 = si0;
    for (int i = t; i < nx; i += 256) {
        swx[i] = g_wx[b][i];
        scolm[i] = g_colm[b][i];
        scell[i] = g_cellx[b][i];
    }
    for (int i = t; i < ny; i += 256) {
        swy[i] = g_wy[b][i0 + i];
        srowm[i] = g_rowm[b][i0 + i];
    }
    __syncthreads();

    int pairs = nx * ny;
    for (int p = t; p < pairs; p += 256) {
        int ys = p / nx, xs = p - ys * nx;
        unsigned m = srowm[ys] & scolm[xs];
        float v = 0.f;
        while (m) {
            int i = __ffs(m) - 1;
            v += sconf[i];
            m &= m - 1;
        }
        float sg = __fdividef(1.f, 1.f + __expf(-v));
        atomicAdd(&stile[scell[xs]], swy[ys] * swx[xs] * sg);
    }
    __syncthreads();
    if (t < 28) g_sum28[b][band * 28 + t] = stile[t];
}

// -------- K2: logits + last-block softmax epilogue ------------------------
// grid = (C/8, B, 3), 256 threads = 8 warps; each warp does one channel.
__global__ void logits_kernel(const float* __restrict__ f0,
                              const float* __restrict__ f1,
                              const float* __restrict__ f2) {
    int l = blockIdx.z, b = blockIdx.y;
    __shared__ __align__(16) float satt[HW0];

    int warp = threadIdx.x >> 5, lane = threadIdx.x & 31;
    int c = blockIdx.x * 8 + warp;
    int t = threadIdx.x;
    float acc = 0.f;
    const float* gs = g_sum28[b];

    if (l == 0) {
        for (int i = t; i < HW0; i += 256) satt[i] = gs[i] * (1.f / 64.f);
        __syncthreads();
        const float4* fp = (const float4*)(f0 + ((size_t)(b * C + c)) * HW0);
        const float4* ap = (const float4*)satt;
#pragma unroll
        for (int k = 0; k < 7; k++) {
            int i = lane + 32 * k;
            if (i < HW0 / 4) {
                float4 v = fp[i], a = ap[i];
                acc = fmaf(v.x, a.x, acc);
                acc = fmaf(v.y, a.y, acc);
                acc = fmaf(v.z, a.z, acc);
                acc = fmaf(v.w, a.w, acc);
            }
        }
    } else if (l == 1) {
        if (t < HW1) {
            int ay = t / 14, ax = t % 14;
            int base = (2 * ay) * 28 + 2 * ax;
            float s = gs[base] + gs[base + 1] + gs[base + 28] + gs[base + 29];
            satt[t] = s * (1.f / 256.f);
        }
        __syncthreads();
        const float4* fp = (const float4*)(f1 + ((size_t)(b * C + c)) * HW1);
        const float4* ap = (const float4*)satt;
#pragma unroll
        for (int k = 0; k < 2; k++) {
            int i = lane + 32 * k;
            if (i < HW1 / 4) {
                float4 v = fp[i], a = ap[i];
                acc = fmaf(v.x, a.x, acc);
                acc = fmaf(v.y, a.y, acc);
                acc = fmaf(v.z, a.z, acc);
                acc = fmaf(v.w, a.w, acc);
            }
        }
    } else {
        if (t < HW2) {
            int ay = t / 7, ax = t % 7;
            float s = 0.f;
#pragma unroll
            for (int iy = 0; iy < 4; iy++)
#pragma unroll
                for (int ix = 0; ix < 4; ix++)
                    s += gs[(4 * ay + iy) * 28 + 4 * ax + ix];
            satt[t] = s * (1.f / 1024.f);
        }
        __syncthreads();
        const float* fp = f2 + ((size_t)(b * C + c)) * HW2;
#pragma unroll
        for (int k = 0; k < 2; k++) {
            int i = lane + 32 * k;
            if (i < HW2) acc = fmaf(fp[i], satt[i], acc);
        }
    }

#pragma unroll
    for (int o = 16; o > 0; o >>= 1) acc += __shfl_xor_sync(0xffffffffu, acc, o);
    int base = (l * B + b) * C;
    if (lane == 0) g_logits[base + c] = acc;
    __syncthreads();

    // ---- last-block softmax epilogue ----
    __shared__ int is_last;
    if (t == 0) {
        __threadfence();
        is_last = (atomicAdd(&g_cnt[l * B + b], 1) == (C / 8) - 1);
    }
    __syncthreads();
    if (!is_last) return;
    if (t == 0) g_cnt[l * B + b] = 0;   // reset for next graph replay

    __shared__ float red[8];
    __shared__ float smax, ssum;
    float x0 = g_logits[base + t];
    float x1 = g_logits[base + t + 256];
    float m = fmaxf(x0, x1);
#pragma unroll
    for (int o = 16; o > 0; o >>= 1) m = fmaxf(m, __shfl_xor_sync(0xffffffffu, m, o));
    if (lane == 0) red[warp] = m;
    __syncthreads();
    if (t == 0) {
        float mm = red[0];
#pragma unroll
        for (int i = 1; i < 8; i++) mm = fmaxf(mm, red[i]);
        smax = mm;
    }
    __syncthreads();
    float e0 = __expf(x0 - smax), e1 = __expf(x1 - smax);
    float s = e0 + e1;
#pragma unroll
    for (int o = 16; o > 0; o >>= 1) s += __shfl_xor_sync(0xffffffffu, s, o);
    if (lane == 0) red[warp] = s;
    __syncthreads();
    if (t == 0) {
        float ss = 0.f;
#pragma unroll
        for (int i = 0; i < 8; i++) ss += red[i];
        ssum = ss;
    }
    __syncthreads();
    float inv = __fdividef(1.f, ssum);
    g_weights[base + t] = e0 * inv;
    g_weights[base + t + 256] = e1 * inv;
}

// ---------------- K3: pure streaming scale, warp-per-row -----------------
__global__ void scale_kernel(const float* __restrict__ f0,
                             const float* __restrict__ f1,
                             const float* __restrict__ f2,
                             float* __restrict__ out) {
    int l = blockIdx.y;
    int warp = threadIdx.x >> 5, lane = threadIdx.x & 31;
    int row = blockIdx.x * 16 + warp;   // 0 .. B*C-1
    int b = row >> 9, c = row & (C - 1);
    float w = __ldg(&g_weights[(l * B + b) * C + c]);

    if (l == 0) {
        const float4* src = (const float4*)(f0 + (size_t)row * HW0);
        float4* dst = (float4*)(out + (size_t)b * OUT_ROW + (size_t)c * HW0);
#pragma unroll
        for (int k = 0; k < 7; k++) {
            int i = lane + 32 * k;
            if (i < HW0 / 4) {
                float4 v = src[i];
                v.x *= w; v.y *= w; v.z *= w; v.w *= w;
                dst[i] = v;
            }
        }
    } else if (l == 1) {
        const float4* src = (const float4*)(f1 + (size_t)row * HW1);
        float4* dst = (float4*)(out + (size_t)b * OUT_ROW + OUT_OFF1 + (size_t)c * HW1);
#pragma unroll
        for (int k = 0; k < 2; k++) {
            int i = lane + 32 * k;
            if (i < HW1 / 4) {
                float4 v = src[i];
                v.x *= w; v.y *= w; v.z *= w; v.w *= w;
                dst[i] = v;
            }
        }
    } else {
        const float* src = f2 + (size_t)row * HW2;
        float* dst = out + (size_t)b * OUT_ROW + OUT_OFF2 + (size_t)c * HW2;
#pragma unroll
        for (int k = 0; k < 2; k++) {
            int i = lane + 32 * k;
            if (i < HW2) dst[i] = src[i] * w;
        }
    }
}

extern "C" void kernel_launch(void* const* d_in, const int* in_sizes, int n_in,
                              void* d_out, int out_size) {
    const float* confs = (const float*)d_in[0];
    const float* boxes = (const float*)d_in[1];
    const float* f0 = (const float*)d_in[2];
    const float* f1 = (const float*)d_in[3];
    const float* f2 = (const float*)d_in[4];
    float* out = (float*)d_out;

    seg_kernel<<<B, 448>>>(boxes);
    tile_kernel<<<dim3(28, B), 256>>>(confs);
    logits_kernel<<<dim3(C / 8, B, 3), 256>>>(f0, f1, f2);
    scale_kernel<<<dim3(B * C / 16, 3), 512>>>(f0, f1, f2, out);
}

// round 9
// speedup vs baseline: 1.8097x; 1.0805x over previous
#include <cuda_runtime.h>
#include <math.h>

#define B 16
#define N 32
#define C 512
#define FEAT 224

#define HW0 784
#define HW1 196
#define HW2 49
#define OUT_ROW (C*(HW0+HW1+HW2))
#define OUT_OFF1 (C*HW0)         // 401408
#define OUT_OFF2 (C*(HW0+HW1))   // 501760
#define MAXSEG 96

// ---------------- scratch (no allocations allowed) ----------------
__device__ float    g_wx[B][MAXSEG];
__device__ unsigned g_colm[B][MAXSEG];
__device__ int      g_cellx[B][MAXSEG];
__device__ int      g_nsegx[B];
__device__ float    g_sum28[B][HW0];   // per-8x8-tile sum of sigmoid
__device__ float    g_logits[3 * B * C];
__device__ float    g_weights[3 * B * C];
__device__ int      g_cnt[3 * B];      // zero-init; reset by last block each run

// ---------------- K0: per-batch x-segment table (x-axis only) -----------
// grid = B, 224 threads. Breakpoints = box x-edges U multiples of 8.
__global__ void seg_kernel(const float* __restrict__ boxes) {
    int b = blockIdx.x;
    int t = threadIdx.x;
    int lane = t & 31, wl = t >> 5;

    __shared__ int sbx[N * 4];
    __shared__ unsigned char flag[FEAT];
    __shared__ int segstart[MAXSEG];
    __shared__ int woff[8];
    __shared__ int snseg;

    if (t < N * 4) sbx[t] = (int)floorf(boxes[b * N * 4 + t] * (float)FEAT);
    flag[t] = ((t & 7) == 0);
    __syncthreads();

    if (t < N) {
        int e1 = sbx[4 * t], e2 = sbx[4 * t + 2];
        if (e1 >= 0 && e1 < FEAT) flag[e1] = 1;
        if (e2 >= 0 && e2 < FEAT) flag[e2] = 1;
    }
    __syncthreads();

    unsigned bal = __ballot_sync(0xffffffffu, flag[t] != 0);
    if (lane == 0) woff[wl] = __popc(bal);
    __syncthreads();
    if (t == 0) {
        int run = 0;
        for (int i = 0; i < 7; i++) { int c = woff[i]; woff[i] = run; run += c; }
        snseg = run;
    }
    __syncthreads();
    if (flag[t])
        segstart[woff[wl] + __popc(bal & ((1u << lane) - 1u))] = t;
    __syncthreads();

    int nseg = snseg;
    if (t < nseg) {
        int s = segstart[t];
        int wd = ((t + 1 < nseg) ? segstart[t + 1] : FEAT) - s;
        unsigned m = 0;
#pragma unroll
        for (int n = 0; n < N; n++)
            m |= (unsigned)(s >= sbx[4 * n] && s < sbx[4 * n + 2]) << n;
        g_wx[b][t] = (float)wd;
        g_colm[b][t] = m;
        g_cellx[b][t] = s >> 3;
    }
    if (t == 0) g_nsegx[b] = nseg;
}

// ---------------- K1: rectangle eval -> 8x8 tile sums ------------------
// grid = (28 bands, B), 256 threads. Row masks for the band's 8 rows are
// computed inline and merged (equal adjacent masks coalesce), keeping the
// pair count at nx * ~3.3.
__global__ void tile_kernel(const float* __restrict__ confs,
                            const float* __restrict__ boxes) {
    int band = blockIdx.x, b = blockIdx.y;
    int t = threadIdx.x;
    __shared__ int sbx[N * 4];
    __shared__ float swx[MAXSEG];
    __shared__ unsigned scolm[MAXSEG];
    __shared__ int scell[MAXSEG];
    __shared__ unsigned rm8[8];
    __shared__ float swy[8];
    __shared__ unsigned srowm[8];
    __shared__ float sconf[N];
    __shared__ float stile[28];
    __shared__ int snx, sny;

    if (t < N * 4) sbx[t] = (int)floorf(boxes[b * N * 4 + t] * (float)FEAT);
    if (t < N) sconf[t] = confs[b * N + t];
    if (t == 0) snx = g_nsegx[b];
    if (t < 28) stile[t] = 0.f;
    __syncthreads();

    if (t < 8) {
        int y = band * 8 + t;
        unsigned rm = 0;
#pragma unroll
        for (int n = 0; n < N; n++)
            rm |= (unsigned)(y >= sbx[4 * n + 1] && y < sbx[4 * n + 3]) << n;
        rm8[t] = rm;
    }
    int nx = snx;
    for (int i = t; i < nx; i += 256) {
        swx[i] = g_wx[b][i];
        scolm[i] = g_colm[b][i];
        scell[i] = g_cellx[b][i];
    }
    __syncthreads();
    if (t == 0) {            // merge equal adjacent row masks
        int ny = 0;
        for (int i = 0; i < 8; i++) {
            if (i == 0 || rm8[i] != rm8[i - 1]) {
                srowm[ny] = rm8[i];
                swy[ny] = 1.f;
                ny++;
            } else {
                swy[ny - 1] += 1.f;
            }
        }
        sny = ny;
    }
    __syncthreads();

    int ny = sny;
    int pairs = nx * ny;
    for (int p = t; p < pairs; p += 256) {
        int ys = p / nx, xs = p - ys * nx;
        unsigned m = srowm[ys] & scolm[xs];
        float v = 0.f;
        while (m) {
            int i = __ffs(m) - 1;
            v += sconf[i];
            m &= m - 1;
        }
        float sg = __fdividef(1.f, 1.f + __expf(-v));
        atomicAdd(&stile[scell[xs]], swy[ys] * swx[xs] * sg);
    }
    __syncthreads();
    if (t < 28) g_sum28[b][band * 28 + t] = stile[t];
}

// -------- K2: logits (2 channels/warp) + last-block softmax epilogue ------
// grid = (C/16, B, 3), 256 threads = 8 warps; each warp does 2 channels.
__global__ void logits_kernel(const float* __restrict__ f0,
                              const float* __restrict__ f1,
                              const float* __restrict__ f2) {
    int l = blockIdx.z, b = blockIdx.y;
    __shared__ __align__(16) float satt[HW0];

    int warp = threadIdx.x >> 5, lane = threadIdx.x & 31;
    int c0 = blockIdx.x * 16 + warp * 2;
    int t = threadIdx.x;
    float acc0 = 0.f, acc1 = 0.f;
    const float* gs = g_sum28[b];

    if (l == 0) {
        for (int i = t; i < HW0; i += 256) satt[i] = gs[i] * (1.f / 64.f);
        __syncthreads();
        const float4* fp0 = (const float4*)(f0 + ((size_t)(b * C + c0)) * HW0);
        const float4* fp1 = fp0 + (HW0 / 4);
        const float4* ap = (const float4*)satt;
#pragma unroll
        for (int k = 0; k < 7; k++) {
            int i = lane + 32 * k;
            if (i < HW0 / 4) {
                float4 v0 = fp0[i], v1 = fp1[i], a = ap[i];
                acc0 = fmaf(v0.x, a.x, acc0);
                acc0 = fmaf(v0.y, a.y, acc0);
                acc0 = fmaf(v0.z, a.z, acc0);
                acc0 = fmaf(v0.w, a.w, acc0);
                acc1 = fmaf(v1.x, a.x, acc1);
                acc1 = fmaf(v1.y, a.y, acc1);
                acc1 = fmaf(v1.z, a.z, acc1);
                acc1 = fmaf(v1.w, a.w, acc1);
            }
        }
    } else if (l == 1) {
        if (t < HW1) {
            int ay = t / 14, ax = t % 14;
            int base = (2 * ay) * 28 + 2 * ax;
            float s = gs[base] + gs[base + 1] + gs[base + 28] + gs[base + 29];
            satt[t] = s * (1.f / 256.f);
        }
        __syncthreads();
        const float4* fp0 = (const float4*)(f1 + ((size_t)(b * C + c0)) * HW1);
        const float4* fp1 = fp0 + (HW1 / 4);
        const float4* ap = (const float4*)satt;
#pragma unroll
        for (int k = 0; k < 2; k++) {
            int i = lane + 32 * k;
            if (i < HW1 / 4) {
                float4 v0 = fp0[i], v1 = fp1[i], a = ap[i];
                acc0 = fmaf(v0.x, a.x, acc0);
                acc0 = fmaf(v0.y, a.y, acc0);
                acc0 = fmaf(v0.z, a.z, acc0);
                acc0 = fmaf(v0.w, a.w, acc0);
                acc1 = fmaf(v1.x, a.x, acc1);
                acc1 = fmaf(v1.y, a.y, acc1);
                acc1 = fmaf(v1.z, a.z, acc1);
                acc1 = fmaf(v1.w, a.w, acc1);
            }
        }
    } else {
        if (t < HW2) {
            int ay = t / 7, ax = t % 7;
            float s = 0.f;
#pragma unroll
            for (int iy = 0; iy < 4; iy++)
#pragma unroll
                for (int ix = 0; ix < 4; ix++)
                    s += gs[(4 * ay + iy) * 28 + 4 * ax + ix];
            satt[t] = s * (1.f / 1024.f);
        }
        __syncthreads();
        const float* fp0 = f2 + ((size_t)(b * C + c0)) * HW2;
        const float* fp1 = fp0 + HW2;
#pragma unroll
        for (int k = 0; k < 2; k++) {
            int i = lane + 32 * k;
            if (i < HW2) {
                float a = satt[i];
                acc0 = fmaf(fp0[i], a, acc0);
                acc1 = fmaf(fp1[i], a, acc1);
            }
        }
    }

#pragma unroll
    for (int o = 16; o > 0; o >>= 1) {
        acc0 += __shfl_xor_sync(0xffffffffu, acc0, o);
        acc1 += __shfl_xor_sync(0xffffffffu, acc1, o);
    }
    int base = (l * B + b) * C;
    if (lane == 0) {
        g_logits[base + c0] = acc0;
        g_logits[base + c0 + 1] = acc1;
    }
    __syncthreads();

    // ---- last-block softmax epilogue ----
    __shared__ int is_last;
    if (t == 0) {
        __threadfence();
        is_last = (atomicAdd(&g_cnt[l * B + b], 1) == (C / 16) - 1);
    }
    __syncthreads();
    if (!is_last) return;
    if (t == 0) g_cnt[l * B + b] = 0;   // reset for next graph replay

    __shared__ float red[8];
    __shared__ float smax, ssum;
    float x0 = g_logits[base + t];
    float x1 = g_logits[base + t + 256];
    float m = fmaxf(x0, x1);
#pragma unroll
    for (int o = 16; o > 0; o >>= 1) m = fmaxf(m, __shfl_xor_sync(0xffffffffu, m, o));
    if (lane == 0) red[warp] = m;
    __syncthreads();
    if (t == 0) {
        float mm = red[0];
#pragma unroll
        for (int i = 1; i < 8; i++) mm = fmaxf(mm, red[i]);
        smax = mm;
    }
    __syncthreads();
    float e0 = __expf(x0 - smax), e1 = __expf(x1 - smax);
    float s = e0 + e1;
#pragma unroll
    for (int o = 16; o > 0; o >>= 1) s += __shfl_xor_sync(0xffffffffu, s, o);
    if (lane == 0) red[warp] = s;
    __syncthreads();
    if (t == 0) {
        float ss = 0.f;
#pragma unroll
        for (int i = 0; i < 8; i++) ss += red[i];
        ssum = ss;
    }
    __syncthreads();
    float inv = __fdividef(1.f, ssum);
    g_weights[base + t] = e0 * inv;
    g_weights[base + t + 256] = e1 * inv;
}

// ---------------- K3: pure streaming scale, warp-per-row -----------------
// __stcs stores: output is never re-read; evict-first keeps feat lines in L2.
__global__ void scale_kernel(const float* __restrict__ f0,
                             const float* __restrict__ f1,
                             const float* __restrict__ f2,
                             float* __restrict__ out) {
    int l = blockIdx.y;
    int warp = threadIdx.x >> 5, lane = threadIdx.x & 31;
    int row = blockIdx.x * 16 + warp;   // 0 .. B*C-1
    int b = row >> 9, c = row & (C - 1);
    float w = __ldg(&g_weights[(l * B + b) * C + c]);

    if (l == 0) {
        const float4* src = (const float4*)(f0 + (size_t)row * HW0);
        float4* dst = (float4*)(out + (size_t)b * OUT_ROW + (size_t)c * HW0);
#pragma unroll
        for (int k = 0; k < 7; k++) {
            int i = lane + 32 * k;
            if (i < HW0 / 4) {
                float4 v = src[i];
                v.x *= w; v.y *= w; v.z *= w; v.w *= w;
                __stcs(&dst[i], v);
            }
        }
    } else if (l == 1) {
        const float4* src = (const float4*)(f1 + (size_t)row * HW1);
        float4* dst = (float4*)(out + (size_t)b * OUT_ROW + OUT_OFF1 + (size_t)c * HW1);
#pragma unroll
        for (int k = 0; k < 2; k++) {
            int i = lane + 32 * k;
            if (i < HW1 / 4) {
                float4 v = src[i];
                v.x *= w; v.y *= w; v.z *= w; v.w *= w;
                __stcs(&dst[i], v);
            }
        }
    } else {
        const float* src = f2 + (size_t)row * HW2;
        float* dst = out + (size_t)b * OUT_ROW + OUT_OFF2 + (size_t)c * HW2;
#pragma unroll
        for (int k = 0; k < 2; k++) {
            int i = lane + 32 * k;
            if (i < HW2) __stcs(&dst[i], src[i] * w);
        }
    }
}

extern "C" void kernel_launch(void* const* d_in, const int* in_sizes, int n_in,
                              void* d_out, int out_size) {
    const float* confs = (const float*)d_in[0];
    const float* boxes = (const float*)d_in[1];
    const float* f0 = (const float*)d_in[2];
    const float* f1 = (const float*)d_in[3];
    const float* f2 = (const float*)d_in[4];
    float* out = (float*)d_out;

    seg_kernel<<<B, 224>>>(boxes);
    tile_kernel<<<dim3(28, B), 256>>>(confs, boxes);
    logits_kernel<<<dim3(C / 16, B, 3), 256>>>(f0, f1, f2);
    scale_kernel<<<dim3(B * C / 16, 3), 512>>>(f0, f1, f2, out);
}